// round 4
// baseline (speedup 1.0000x reference)
#include <cuda_runtime.h>
#include <cuda_bf16.h>

// Problem constants
#define B_   8
#define C_   64
#define H_   128
#define W_   128
#define CO_  18      // offset channels
#define G_   8       // groups
#define CG_  8       // channels per group (in & out)
#define KK_  9
#define HW_  (H_*W_)

// Scratch
__device__ float g_off[B_ * H_ * W_ * CO_];        // [b][h][w][18]
__device__ float g_xt [B_ * C_ * HW_];             // NHWC8: [b][g][hw][ci(8)]

// ---------------------------------------------------------------------------
// Kernel 1: offset = prelu(conv3x3(x, ow) + ob), and export x as NHWC8 (g_xt).
// 32x16 pixel tile, 256 threads, 2 pixels/thread (rows ty and ty+16).
// Weights: scalar broadcast LDS, amortized over 2 pixels.
// ---------------------------------------------------------------------------
#define T1H 32
#define T1W 16
__global__ __launch_bounds__(256) void offset_conv_kernel(
    const float* __restrict__ x,     // [B,64,H,W]
    const float* __restrict__ ow,    // [18,64,3,3]
    const float* __restrict__ ob,    // [18]
    const float* __restrict__ pa)    // [1]
{
    __shared__ float sx[8][T1H + 2][T1W + 2];   // 8 ch x 34 x 18
    __shared__ float swt[CO_][8][KK_];

    const int b  = blockIdx.z;
    const int h0 = blockIdx.y * T1H;
    const int w0 = blockIdx.x * T1W;
    const int ty = threadIdx.x / T1W;   // 0..15
    const int tx = threadIdx.x % T1W;   // 0..15

    float acc0[CO_], acc1[CO_];
#pragma unroll
    for (int co = 0; co < CO_; co++) { float bb = __ldg(ob + co); acc0[co] = bb; acc1[co] = bb; }

    for (int cc = 0; cc < C_ / 8; cc++) {
        __syncthreads();
        // load 8-channel halo tile (34x18 per channel), zero-padded
        for (int i = threadIdx.x; i < 8 * (T1H + 2) * (T1W + 2); i += 256) {
            int ci = i / ((T1H + 2) * (T1W + 2));
            int r  = (i / (T1W + 2)) % (T1H + 2);
            int c  = i % (T1W + 2);
            int gh = h0 - 1 + r;
            int gw = w0 - 1 + c;
            float v = 0.f;
            if (gh >= 0 && gh < H_ && gw >= 0 && gw < W_)
                v = x[(((size_t)b * C_ + cc * 8 + ci) * H_ + gh) * W_ + gw];
            sx[ci][r][c] = v;
        }
        // load weight chunk [co][ci][k]
        for (int i = threadIdx.x; i < CO_ * 8 * KK_; i += 256) {
            int co = i / (8 * KK_);
            int ci = (i / KK_) % 8;
            int k  = i % KK_;
            swt[co][ci][k] = ow[((co * C_ + cc * 8 + ci) * KK_) + k];
        }
        __syncthreads();

#pragma unroll
        for (int ci = 0; ci < 8; ci++) {
#pragma unroll
            for (int k = 0; k < KK_; k++) {
                float v0 = sx[ci][ty      + k / 3][tx + k % 3];
                float v1 = sx[ci][ty + 16 + k / 3][tx + k % 3];
#pragma unroll
                for (int co = 0; co < CO_; co++) {
                    float wv = swt[co][ci][k];
                    acc0[co] += v0 * wv;
                    acc1[co] += v1 * wv;
                }
            }
        }

        // export this chunk (= group cc) of the tile interior as NHWC8
#pragma unroll
        for (int p = 0; p < 2; p++) {
            int row = ty + 16 * p;
            float4 lo, hi;
            lo.x = sx[0][row + 1][tx + 1];
            lo.y = sx[1][row + 1][tx + 1];
            lo.z = sx[2][row + 1][tx + 1];
            lo.w = sx[3][row + 1][tx + 1];
            hi.x = sx[4][row + 1][tx + 1];
            hi.y = sx[5][row + 1][tx + 1];
            hi.z = sx[6][row + 1][tx + 1];
            hi.w = sx[7][row + 1][tx + 1];
            size_t o = ((size_t)(b * G_ + cc) * HW_ + (size_t)(h0 + row) * W_ + (w0 + tx)) * 8;
            *(float4*)(g_xt + o)     = lo;
            *(float4*)(g_xt + o + 4) = hi;
        }
    }

    const float a = pa[0];
#pragma unroll
    for (int p = 0; p < 2; p++) {
        int row = ty + 16 * p;
        float* o = g_off + (((size_t)b * H_ + (h0 + row)) * W_ + (w0 + tx)) * CO_;
#pragma unroll
        for (int co = 0; co < CO_; co++) {
            float v = (p == 0) ? acc0[co] : acc1[co];
            o[co] = v > 0.f ? v : a * v;
        }
    }
}

// ---------------------------------------------------------------------------
// Kernel 2: deformable conv over NHWC8 x. Block = 32 pixels x 8 groups.
// Phase A: (pixel, tap) -> 4 corner indices + validity-folded weights in smem.
// Phase B: thread (pxl, g): per tap, gather 8 channels per corner via 2x
//          LDG.128, blend into s[8], then 8x8 FFMA with smem weights.
// ---------------------------------------------------------------------------
__global__ __launch_bounds__(256) void dconv_kernel(
    const float* __restrict__ dw,   // [64,8,3,3] = [g][co][ci][k]
    const float* __restrict__ db,   // [64]
    float* __restrict__ out)        // [B,64,H,W]
{
    __shared__ float sw[G_ * CG_ * KK_ * CG_];  // [g][ci][k][co]
    __shared__ float sb[C_];
    __shared__ int   s_idx[KK_][4][32];
    __shared__ float s_cw[KK_][4][32];

    for (int i = threadIdx.x; i < G_ * CG_ * CG_ * KK_; i += 256) {
        int co = i % CG_;
        int k  = (i / CG_) % KK_;
        int ci = (i / (CG_ * KK_)) % CG_;
        int g  = i / (CG_ * KK_ * CG_);
        sw[i] = dw[((g * CG_ + co) * CG_ + ci) * KK_ + k];
    }
    if (threadIdx.x < C_) sb[threadIdx.x] = db[threadIdx.x];

    const int pix0 = blockIdx.x * 32;

    // ---- Phase A ----
    for (int u = threadIdx.x; u < 32 * KK_; u += 256) {
        const int pxl = u & 31;
        const int k   = u >> 5;
        const int pix = pix0 + pxl;
        const int hw  = pix % HW_;
        const int h   = hw / W_;
        const int w   = hw % W_;

        const float* op = g_off + (size_t)pix * CO_ + 2 * k;
        float dy = op[0];
        float dx = op[1];
        float py = (float)(h + (k / 3) - 1) + dy;
        float px = (float)(w + (k % 3) - 1) + dx;
        float y0f = floorf(py);
        float x0f = floorf(px);
        int   y0  = (int)y0f;
        int   x0  = (int)x0f;
        float ly = py - y0f, lx = px - x0f;
        float hy = 1.f - ly, hx = 1.f - lx;

        int y1 = y0 + 1, x1 = x0 + 1;
        bool vy0 = (y0 >= 0) & (y0 < H_);
        bool vy1 = (y1 >= 0) & (y1 < H_);
        bool vx0 = (x0 >= 0) & (x0 < W_);
        bool vx1 = (x1 >= 0) & (x1 < W_);

        int cy0 = min(max(y0, 0), H_ - 1);
        int cy1 = min(max(y1, 0), H_ - 1);
        int cx0 = min(max(x0, 0), W_ - 1);
        int cx1 = min(max(x1, 0), W_ - 1);

        s_idx[k][0][pxl] = cy0 * W_ + cx0;  s_cw[k][0][pxl] = (vy0 & vx0) ? hy * hx : 0.f;
        s_idx[k][1][pxl] = cy0 * W_ + cx1;  s_cw[k][1][pxl] = (vy0 & vx1) ? hy * lx : 0.f;
        s_idx[k][2][pxl] = cy1 * W_ + cx0;  s_cw[k][2][pxl] = (vy1 & vx0) ? ly * hx : 0.f;
        s_idx[k][3][pxl] = cy1 * W_ + cx1;  s_cw[k][3][pxl] = (vy1 & vx1) ? ly * lx : 0.f;
    }
    __syncthreads();

    // ---- Phase B ----
    const int tx  = threadIdx.x & 31;   // pixel lane
    const int g   = threadIdx.x >> 5;   // group
    const int pix = pix0 + tx;
    const int b   = pix / HW_;
    const int hw  = pix % HW_;

    float acc[CG_];
#pragma unroll
    for (int co = 0; co < CG_; co++) acc[co] = sb[g * CG_ + co];

    const float* wg = sw + g * CG_ * KK_ * CG_;                  // [ci][k][co]
    const float* xb = g_xt + (size_t)(b * G_ + g) * HW_ * 8;     // [hw][ci8]

#pragma unroll
    for (int k = 0; k < KK_; k++) {
        float s[CG_];
#pragma unroll
        for (int ci = 0; ci < CG_; ci++) s[ci] = 0.f;

#pragma unroll
        for (int c = 0; c < 4; c++) {
            const int   id = s_idx[k][c][tx];
            const float wc = s_cw[k][c][tx];
            const float4* p = (const float4*)(xb + (size_t)id * 8);
            float4 xa = __ldg(p);
            float4 xc = __ldg(p + 1);
            s[0] += wc * xa.x;  s[1] += wc * xa.y;
            s[2] += wc * xa.z;  s[3] += wc * xa.w;
            s[4] += wc * xc.x;  s[5] += wc * xc.y;
            s[6] += wc * xc.z;  s[7] += wc * xc.w;
        }

#pragma unroll
        for (int ci = 0; ci < CG_; ci++) {
            const float4* wv = (const float4*)(wg + (ci * KK_ + k) * CG_);
            float4 w0 = wv[0];
            float4 w1 = wv[1];
            float v = s[ci];
            acc[0] += v * w0.x;  acc[1] += v * w0.y;
            acc[2] += v * w0.z;  acc[3] += v * w0.w;
            acc[4] += v * w1.x;  acc[5] += v * w1.y;
            acc[6] += v * w1.z;  acc[7] += v * w1.w;
        }
    }

    float* ob = out + ((size_t)b * C_ + g * CG_) * HW_ + hw;
#pragma unroll
    for (int co = 0; co < CG_; co++)
        ob[co * HW_] = acc[co];
}

// ---------------------------------------------------------------------------
// Launch
// ---------------------------------------------------------------------------
extern "C" void kernel_launch(void* const* d_in, const int* in_sizes, int n_in,
                              void* d_out, int out_size)
{
    const float* x    = (const float*)d_in[0];  // [8,64,128,128]
    const float* ow   = (const float*)d_in[1];  // [18,64,3,3]
    const float* ob   = (const float*)d_in[2];  // [18]
    const float* pa   = (const float*)d_in[3];  // [1]
    const float* dwgt = (const float*)d_in[4];  // [64,8,3,3]
    const float* dbia = (const float*)d_in[5];  // [64]
    float* out = (float*)d_out;

    dim3 g1(W_ / T1W, H_ / T1H, B_);            // (8, 4, 8)
    offset_conv_kernel<<<g1, 256>>>(x, ow, ob, pa);

    const int blocks = (B_ * HW_) / 32;         // 4096
    dconv_kernel<<<blocks, 256>>>(dwgt, dbia, out);
}

// round 5
// speedup vs baseline: 1.0025x; 1.0025x over previous
#include <cuda_runtime.h>
#include <cuda_bf16.h>

// Problem constants
#define B_   8
#define C_   64
#define H_   128
#define W_   128
#define CO_  18      // offset channels
#define G_   8       // groups
#define CG_  8       // channels per group (in & out)
#define KK_  9
#define HW_  (H_*W_)

// Scratch
__device__ float g_off[B_ * H_ * W_ * CO_];        // [b][h][w][18]
__device__ float g_xt [B_ * C_ * HW_];             // NHWC8: [b][g][hw][ci(8)]

// ---------------------------------------------------------------------------
// Kernel 1: offset = prelu(conv3x3(x, ow) + ob), and export x as NHWC8 (g_xt).
// 32x16 pixel tile, 256 threads, 2 pixels/thread (rows ty and ty+16).
// Weights: scalar broadcast LDS, amortized over 2 pixels.
// ---------------------------------------------------------------------------
#define T1H 32
#define T1W 16
__global__ __launch_bounds__(256) void offset_conv_kernel(
    const float* __restrict__ x,     // [B,64,H,W]
    const float* __restrict__ ow,    // [18,64,3,3]
    const float* __restrict__ ob,    // [18]
    const float* __restrict__ pa)    // [1]
{
    __shared__ float sx[8][T1H + 2][T1W + 2];   // 8 ch x 34 x 18
    __shared__ float swt[CO_][8][KK_];

    const int b  = blockIdx.z;
    const int h0 = blockIdx.y * T1H;
    const int w0 = blockIdx.x * T1W;
    const int ty = threadIdx.x / T1W;   // 0..15
    const int tx = threadIdx.x % T1W;   // 0..15

    float acc0[CO_], acc1[CO_];
#pragma unroll
    for (int co = 0; co < CO_; co++) { float bb = __ldg(ob + co); acc0[co] = bb; acc1[co] = bb; }

    for (int cc = 0; cc < C_ / 8; cc++) {
        __syncthreads();
        // load 8-channel halo tile (34x18 per channel), zero-padded
        for (int i = threadIdx.x; i < 8 * (T1H + 2) * (T1W + 2); i += 256) {
            int ci = i / ((T1H + 2) * (T1W + 2));
            int r  = (i / (T1W + 2)) % (T1H + 2);
            int c  = i % (T1W + 2);
            int gh = h0 - 1 + r;
            int gw = w0 - 1 + c;
            float v = 0.f;
            if (gh >= 0 && gh < H_ && gw >= 0 && gw < W_)
                v = x[(((size_t)b * C_ + cc * 8 + ci) * H_ + gh) * W_ + gw];
            sx[ci][r][c] = v;
        }
        // load weight chunk [co][ci][k]
        for (int i = threadIdx.x; i < CO_ * 8 * KK_; i += 256) {
            int co = i / (8 * KK_);
            int ci = (i / KK_) % 8;
            int k  = i % KK_;
            swt[co][ci][k] = ow[((co * C_ + cc * 8 + ci) * KK_) + k];
        }
        __syncthreads();

#pragma unroll
        for (int ci = 0; ci < 8; ci++) {
#pragma unroll
            for (int k = 0; k < KK_; k++) {
                float v0 = sx[ci][ty      + k / 3][tx + k % 3];
                float v1 = sx[ci][ty + 16 + k / 3][tx + k % 3];
#pragma unroll
                for (int co = 0; co < CO_; co++) {
                    float wv = swt[co][ci][k];
                    acc0[co] += v0 * wv;
                    acc1[co] += v1 * wv;
                }
            }
        }

        // export this chunk (= group cc) of the tile interior as NHWC8
#pragma unroll
        for (int p = 0; p < 2; p++) {
            int row = ty + 16 * p;
            float4 lo, hi;
            lo.x = sx[0][row + 1][tx + 1];
            lo.y = sx[1][row + 1][tx + 1];
            lo.z = sx[2][row + 1][tx + 1];
            lo.w = sx[3][row + 1][tx + 1];
            hi.x = sx[4][row + 1][tx + 1];
            hi.y = sx[5][row + 1][tx + 1];
            hi.z = sx[6][row + 1][tx + 1];
            hi.w = sx[7][row + 1][tx + 1];
            size_t o = ((size_t)(b * G_ + cc) * HW_ + (size_t)(h0 + row) * W_ + (w0 + tx)) * 8;
            *(float4*)(g_xt + o)     = lo;
            *(float4*)(g_xt + o + 4) = hi;
        }
    }

    const float a = pa[0];
#pragma unroll
    for (int p = 0; p < 2; p++) {
        int row = ty + 16 * p;
        float* o = g_off + (((size_t)b * H_ + (h0 + row)) * W_ + (w0 + tx)) * CO_;
#pragma unroll
        for (int co = 0; co < CO_; co++) {
            float v = (p == 0) ? acc0[co] : acc1[co];
            o[co] = v > 0.f ? v : a * v;
        }
    }
}

// ---------------------------------------------------------------------------
// Kernel 2: deformable conv over NHWC8 x. Block = 32 pixels x 8 groups.
// Phase A: (pixel, tap) -> 4 corner indices + validity-folded weights in smem.
// Phase B: thread (pxl, g): per tap, gather 8 channels per corner via 2x
//          LDG.128, blend into s[8], then 8x8 FFMA with smem weights.
// ---------------------------------------------------------------------------
__global__ __launch_bounds__(256) void dconv_kernel(
    const float* __restrict__ dw,   // [64,8,3,3] = [g][co][ci][k]
    const float* __restrict__ db,   // [64]
    float* __restrict__ out)        // [B,64,H,W]
{
    __shared__ float sw[G_ * CG_ * KK_ * CG_];  // [g][ci][k][co]
    __shared__ float sb[C_];
    __shared__ int   s_idx[KK_][4][32];
    __shared__ float s_cw[KK_][4][32];

    for (int i = threadIdx.x; i < G_ * CG_ * CG_ * KK_; i += 256) {
        int co = i % CG_;
        int k  = (i / CG_) % KK_;
        int ci = (i / (CG_ * KK_)) % CG_;
        int g  = i / (CG_ * KK_ * CG_);
        sw[i] = dw[((g * CG_ + co) * CG_ + ci) * KK_ + k];
    }
    if (threadIdx.x < C_) sb[threadIdx.x] = db[threadIdx.x];

    const int pix0 = blockIdx.x * 32;

    // ---- Phase A ----
    for (int u = threadIdx.x; u < 32 * KK_; u += 256) {
        const int pxl = u & 31;
        const int k   = u >> 5;
        const int pix = pix0 + pxl;
        const int hw  = pix % HW_;
        const int h   = hw / W_;
        const int w   = hw % W_;

        const float* op = g_off + (size_t)pix * CO_ + 2 * k;
        float dy = op[0];
        float dx = op[1];
        float py = (float)(h + (k / 3) - 1) + dy;
        float px = (float)(w + (k % 3) - 1) + dx;
        float y0f = floorf(py);
        float x0f = floorf(px);
        int   y0  = (int)y0f;
        int   x0  = (int)x0f;
        float ly = py - y0f, lx = px - x0f;
        float hy = 1.f - ly, hx = 1.f - lx;

        int y1 = y0 + 1, x1 = x0 + 1;
        bool vy0 = (y0 >= 0) & (y0 < H_);
        bool vy1 = (y1 >= 0) & (y1 < H_);
        bool vx0 = (x0 >= 0) & (x0 < W_);
        bool vx1 = (x1 >= 0) & (x1 < W_);

        int cy0 = min(max(y0, 0), H_ - 1);
        int cy1 = min(max(y1, 0), H_ - 1);
        int cx0 = min(max(x0, 0), W_ - 1);
        int cx1 = min(max(x1, 0), W_ - 1);

        s_idx[k][0][pxl] = cy0 * W_ + cx0;  s_cw[k][0][pxl] = (vy0 & vx0) ? hy * hx : 0.f;
        s_idx[k][1][pxl] = cy0 * W_ + cx1;  s_cw[k][1][pxl] = (vy0 & vx1) ? hy * lx : 0.f;
        s_idx[k][2][pxl] = cy1 * W_ + cx0;  s_cw[k][2][pxl] = (vy1 & vx0) ? ly * hx : 0.f;
        s_idx[k][3][pxl] = cy1 * W_ + cx1;  s_cw[k][3][pxl] = (vy1 & vx1) ? ly * lx : 0.f;
    }
    __syncthreads();

    // ---- Phase B ----
    const int tx  = threadIdx.x & 31;   // pixel lane
    const int g   = threadIdx.x >> 5;   // group
    const int pix = pix0 + tx;
    const int b   = pix / HW_;
    const int hw  = pix % HW_;

    float acc[CG_];
#pragma unroll
    for (int co = 0; co < CG_; co++) acc[co] = sb[g * CG_ + co];

    const float* wg = sw + g * CG_ * KK_ * CG_;                  // [ci][k][co]
    const float* xb = g_xt + (size_t)(b * G_ + g) * HW_ * 8;     // [hw][ci8]

#pragma unroll
    for (int k = 0; k < KK_; k++) {
        float s[CG_];
#pragma unroll
        for (int ci = 0; ci < CG_; ci++) s[ci] = 0.f;

#pragma unroll
        for (int c = 0; c < 4; c++) {
            const int   id = s_idx[k][c][tx];
            const float wc = s_cw[k][c][tx];
            const float4* p = (const float4*)(xb + (size_t)id * 8);
            float4 xa = __ldg(p);
            float4 xc = __ldg(p + 1);
            s[0] += wc * xa.x;  s[1] += wc * xa.y;
            s[2] += wc * xa.z;  s[3] += wc * xa.w;
            s[4] += wc * xc.x;  s[5] += wc * xc.y;
            s[6] += wc * xc.z;  s[7] += wc * xc.w;
        }

#pragma unroll
        for (int ci = 0; ci < CG_; ci++) {
            const float4* wv = (const float4*)(wg + (ci * KK_ + k) * CG_);
            float4 w0 = wv[0];
            float4 w1 = wv[1];
            float v = s[ci];
            acc[0] += v * w0.x;  acc[1] += v * w0.y;
            acc[2] += v * w0.z;  acc[3] += v * w0.w;
            acc[4] += v * w1.x;  acc[5] += v * w1.y;
            acc[6] += v * w1.z;  acc[7] += v * w1.w;
        }
    }

    float* ob = out + ((size_t)b * C_ + g * CG_) * HW_ + hw;
#pragma unroll
    for (int co = 0; co < CG_; co++)
        ob[co * HW_] = acc[co];
}

// ---------------------------------------------------------------------------
// Launch
// ---------------------------------------------------------------------------
extern "C" void kernel_launch(void* const* d_in, const int* in_sizes, int n_in,
                              void* d_out, int out_size)
{
    const float* x    = (const float*)d_in[0];  // [8,64,128,128]
    const float* ow   = (const float*)d_in[1];  // [18,64,3,3]
    const float* ob   = (const float*)d_in[2];  // [18]
    const float* pa   = (const float*)d_in[3];  // [1]
    const float* dwgt = (const float*)d_in[4];  // [64,8,3,3]
    const float* dbia = (const float*)d_in[5];  // [64]
    float* out = (float*)d_out;

    dim3 g1(W_ / T1W, H_ / T1H, B_);            // (8, 4, 8)
    offset_conv_kernel<<<g1, 256>>>(x, ow, ob, pa);

    const int blocks = (B_ * HW_) / 32;         // 4096
    dconv_kernel<<<blocks, 256>>>(dwgt, dbia, out);
}

// round 6
// speedup vs baseline: 1.0035x; 1.0010x over previous
#include <cuda_runtime.h>
#include <cuda_bf16.h>

// Problem constants
#define B_   8
#define C_   64
#define H_   128
#define W_   128
#define CO_  18      // offset channels
#define G_   8       // groups
#define CG_  8       // channels per group (in & out)
#define KK_  9
#define HW_  (H_*W_)

// Scratch
__device__ float g_off[B_ * H_ * W_ * CO_];        // [b][h][w][18]
__device__ float g_xt [B_ * C_ * HW_];             // NHWC8: [b][g][hw][ci(8)]

// ---------------------------------------------------------------------------
// Kernel 1: offset = prelu(conv3x3(x, ow) + ob), and export x as NHWC8 (g_xt).
// 32x16 pixel tile, 256 threads, 2 pixels/thread (rows ty and ty+16).
// Weights: scalar broadcast LDS, amortized over 2 pixels.
// ---------------------------------------------------------------------------
#define T1H 32
#define T1W 16
__global__ __launch_bounds__(256) void offset_conv_kernel(
    const float* __restrict__ x,     // [B,64,H,W]
    const float* __restrict__ ow,    // [18,64,3,3]
    const float* __restrict__ ob,    // [18]
    const float* __restrict__ pa)    // [1]
{
    __shared__ float sx[8][T1H + 2][T1W + 2];   // 8 ch x 34 x 18
    __shared__ float swt[CO_][8][KK_];

    const int b  = blockIdx.z;
    const int h0 = blockIdx.y * T1H;
    const int w0 = blockIdx.x * T1W;
    const int ty = threadIdx.x / T1W;   // 0..15
    const int tx = threadIdx.x % T1W;   // 0..15

    float acc0[CO_], acc1[CO_];
#pragma unroll
    for (int co = 0; co < CO_; co++) { float bb = __ldg(ob + co); acc0[co] = bb; acc1[co] = bb; }

    for (int cc = 0; cc < C_ / 8; cc++) {
        __syncthreads();
        // load 8-channel halo tile (34x18 per channel), zero-padded
        for (int i = threadIdx.x; i < 8 * (T1H + 2) * (T1W + 2); i += 256) {
            int ci = i / ((T1H + 2) * (T1W + 2));
            int r  = (i / (T1W + 2)) % (T1H + 2);
            int c  = i % (T1W + 2);
            int gh = h0 - 1 + r;
            int gw = w0 - 1 + c;
            float v = 0.f;
            if (gh >= 0 && gh < H_ && gw >= 0 && gw < W_)
                v = x[(((size_t)b * C_ + cc * 8 + ci) * H_ + gh) * W_ + gw];
            sx[ci][r][c] = v;
        }
        // load weight chunk [co][ci][k]
        for (int i = threadIdx.x; i < CO_ * 8 * KK_; i += 256) {
            int co = i / (8 * KK_);
            int ci = (i / KK_) % 8;
            int k  = i % KK_;
            swt[co][ci][k] = ow[((co * C_ + cc * 8 + ci) * KK_) + k];
        }
        __syncthreads();

#pragma unroll
        for (int ci = 0; ci < 8; ci++) {
#pragma unroll
            for (int k = 0; k < KK_; k++) {
                float v0 = sx[ci][ty      + k / 3][tx + k % 3];
                float v1 = sx[ci][ty + 16 + k / 3][tx + k % 3];
#pragma unroll
                for (int co = 0; co < CO_; co++) {
                    float wv = swt[co][ci][k];
                    acc0[co] += v0 * wv;
                    acc1[co] += v1 * wv;
                }
            }
        }

        // export this chunk (= group cc) of the tile interior as NHWC8
#pragma unroll
        for (int p = 0; p < 2; p++) {
            int row = ty + 16 * p;
            float4 lo, hi;
            lo.x = sx[0][row + 1][tx + 1];
            lo.y = sx[1][row + 1][tx + 1];
            lo.z = sx[2][row + 1][tx + 1];
            lo.w = sx[3][row + 1][tx + 1];
            hi.x = sx[4][row + 1][tx + 1];
            hi.y = sx[5][row + 1][tx + 1];
            hi.z = sx[6][row + 1][tx + 1];
            hi.w = sx[7][row + 1][tx + 1];
            size_t o = ((size_t)(b * G_ + cc) * HW_ + (size_t)(h0 + row) * W_ + (w0 + tx)) * 8;
            *(float4*)(g_xt + o)     = lo;
            *(float4*)(g_xt + o + 4) = hi;
        }
    }

    const float a = pa[0];
#pragma unroll
    for (int p = 0; p < 2; p++) {
        int row = ty + 16 * p;
        float* o = g_off + (((size_t)b * H_ + (h0 + row)) * W_ + (w0 + tx)) * CO_;
#pragma unroll
        for (int co = 0; co < CO_; co++) {
            float v = (p == 0) ? acc0[co] : acc1[co];
            o[co] = v > 0.f ? v : a * v;
        }
    }
}

// ---------------------------------------------------------------------------
// Kernel 2: deformable conv over NHWC8 x. Block = 32 pixels x 8 groups.
// Phase A: (pixel, tap) -> 4 corner indices + validity-folded weights in smem.
// Phase B: thread (pxl, g): per tap, gather 8 channels per corner via 2x
//          LDG.128, blend into s[8], then 8x8 FFMA with smem weights.
// ---------------------------------------------------------------------------
__global__ __launch_bounds__(256) void dconv_kernel(
    const float* __restrict__ dw,   // [64,8,3,3] = [g][co][ci][k]
    const float* __restrict__ db,   // [64]
    float* __restrict__ out)        // [B,64,H,W]
{
    __shared__ float sw[G_ * CG_ * KK_ * CG_];  // [g][ci][k][co]
    __shared__ float sb[C_];
    __shared__ int   s_idx[KK_][4][32];
    __shared__ float s_cw[KK_][4][32];

    for (int i = threadIdx.x; i < G_ * CG_ * CG_ * KK_; i += 256) {
        int co = i % CG_;
        int k  = (i / CG_) % KK_;
        int ci = (i / (CG_ * KK_)) % CG_;
        int g  = i / (CG_ * KK_ * CG_);
        sw[i] = dw[((g * CG_ + co) * CG_ + ci) * KK_ + k];
    }
    if (threadIdx.x < C_) sb[threadIdx.x] = db[threadIdx.x];

    const int pix0 = blockIdx.x * 32;

    // ---- Phase A ----
    for (int u = threadIdx.x; u < 32 * KK_; u += 256) {
        const int pxl = u & 31;
        const int k   = u >> 5;
        const int pix = pix0 + pxl;
        const int hw  = pix % HW_;
        const int h   = hw / W_;
        const int w   = hw % W_;

        const float* op = g_off + (size_t)pix * CO_ + 2 * k;
        float dy = op[0];
        float dx = op[1];
        float py = (float)(h + (k / 3) - 1) + dy;
        float px = (float)(w + (k % 3) - 1) + dx;
        float y0f = floorf(py);
        float x0f = floorf(px);
        int   y0  = (int)y0f;
        int   x0  = (int)x0f;
        float ly = py - y0f, lx = px - x0f;
        float hy = 1.f - ly, hx = 1.f - lx;

        int y1 = y0 + 1, x1 = x0 + 1;
        bool vy0 = (y0 >= 0) & (y0 < H_);
        bool vy1 = (y1 >= 0) & (y1 < H_);
        bool vx0 = (x0 >= 0) & (x0 < W_);
        bool vx1 = (x1 >= 0) & (x1 < W_);

        int cy0 = min(max(y0, 0), H_ - 1);
        int cy1 = min(max(y1, 0), H_ - 1);
        int cx0 = min(max(x0, 0), W_ - 1);
        int cx1 = min(max(x1, 0), W_ - 1);

        s_idx[k][0][pxl] = cy0 * W_ + cx0;  s_cw[k][0][pxl] = (vy0 & vx0) ? hy * hx : 0.f;
        s_idx[k][1][pxl] = cy0 * W_ + cx1;  s_cw[k][1][pxl] = (vy0 & vx1) ? hy * lx : 0.f;
        s_idx[k][2][pxl] = cy1 * W_ + cx0;  s_cw[k][2][pxl] = (vy1 & vx0) ? ly * hx : 0.f;
        s_idx[k][3][pxl] = cy1 * W_ + cx1;  s_cw[k][3][pxl] = (vy1 & vx1) ? ly * lx : 0.f;
    }
    __syncthreads();

    // ---- Phase B ----
    const int tx  = threadIdx.x & 31;   // pixel lane
    const int g   = threadIdx.x >> 5;   // group
    const int pix = pix0 + tx;
    const int b   = pix / HW_;
    const int hw  = pix % HW_;

    float acc[CG_];
#pragma unroll
    for (int co = 0; co < CG_; co++) acc[co] = sb[g * CG_ + co];

    const float* wg = sw + g * CG_ * KK_ * CG_;                  // [ci][k][co]
    const float* xb = g_xt + (size_t)(b * G_ + g) * HW_ * 8;     // [hw][ci8]

#pragma unroll
    for (int k = 0; k < KK_; k++) {
        float s[CG_];
#pragma unroll
        for (int ci = 0; ci < CG_; ci++) s[ci] = 0.f;

#pragma unroll
        for (int c = 0; c < 4; c++) {
            const int   id = s_idx[k][c][tx];
            const float wc = s_cw[k][c][tx];
            const float4* p = (const float4*)(xb + (size_t)id * 8);
            float4 xa = __ldg(p);
            float4 xc = __ldg(p + 1);
            s[0] += wc * xa.x;  s[1] += wc * xa.y;
            s[2] += wc * xa.z;  s[3] += wc * xa.w;
            s[4] += wc * xc.x;  s[5] += wc * xc.y;
            s[6] += wc * xc.z;  s[7] += wc * xc.w;
        }

#pragma unroll
        for (int ci = 0; ci < CG_; ci++) {
            const float4* wv = (const float4*)(wg + (ci * KK_ + k) * CG_);
            float4 w0 = wv[0];
            float4 w1 = wv[1];
            float v = s[ci];
            acc[0] += v * w0.x;  acc[1] += v * w0.y;
            acc[2] += v * w0.z;  acc[3] += v * w0.w;
            acc[4] += v * w1.x;  acc[5] += v * w1.y;
            acc[6] += v * w1.z;  acc[7] += v * w1.w;
        }
    }

    float* ob = out + ((size_t)b * C_ + g * CG_) * HW_ + hw;
#pragma unroll
    for (int co = 0; co < CG_; co++)
        ob[co * HW_] = acc[co];
}

// ---------------------------------------------------------------------------
// Launch
// ---------------------------------------------------------------------------
extern "C" void kernel_launch(void* const* d_in, const int* in_sizes, int n_in,
                              void* d_out, int out_size)
{
    const float* x    = (const float*)d_in[0];  // [8,64,128,128]
    const float* ow   = (const float*)d_in[1];  // [18,64,3,3]
    const float* ob   = (const float*)d_in[2];  // [18]
    const float* pa   = (const float*)d_in[3];  // [1]
    const float* dwgt = (const float*)d_in[4];  // [64,8,3,3]
    const float* dbia = (const float*)d_in[5];  // [64]
    float* out = (float*)d_out;

    dim3 g1(W_ / T1W, H_ / T1H, B_);            // (8, 4, 8)
    offset_conv_kernel<<<g1, 256>>>(x, ow, ob, pa);

    const int blocks = (B_ * HW_) / 32;         // 4096
    dconv_kernel<<<blocks, 256>>>(dwgt, dbia, out);
}